// round 1
// baseline (speedup 1.0000x reference)
#include <cuda_runtime.h>
#include <cstdint>

// RAPiD decode: raw (64,18,128,128) f32 -> pred (64, 3*128*128, 6) f32
// r = raw.reshape(B,3,6,H,W); per cell:
//   px = (sig(r0)+x)/W*img_w ; py = (sig(r1)+y)/H*img_h
//   pw = exp(r2)*aw ; ph = exp(r3)*ah
//   pa = sig(r4)*360-180 ; conf = sig(r5)
// out[b, (a*H+h)*W+w, f]

static constexpr int NB = 64;
static constexpr int NA = 3;
static constexpr int NH = 128;
static constexpr int NW = 128;
static constexpr int HW = NH * NW;          // 16384
static constexpr int CELLS = NB * NA * HW;  // 3,145,728
static constexpr int TPB = 256;

__device__ __forceinline__ float fsig(float x) {
    return __frcp_rn(1.0f + __expf(-x));
}

__global__ void __launch_bounds__(TPB) rapid_decode_kernel(
    const float* __restrict__ raw,
    const float* __restrict__ anchors,
    const int* __restrict__ p_img_h,
    const int* __restrict__ p_img_w,
    float* __restrict__ out)
{
    __shared__ float s[TPB * 6];   // staged in output order

    const int tl = threadIdx.x;
    const int t  = blockIdx.x * TPB + tl;   // cell index over (b, a, h, w)

    // decompose t -> b, a, h, w   (NW=128, NH=128, NA=3)
    const int w = t & (NW - 1);
    const int h = (t >> 7) & (NH - 1);
    const int ahw = t >> 14;        // b*3 + a
    const int a = ahw % 3;
    const int b = ahw / 3;

    const float img_h = (float)__ldg(p_img_h);
    const float img_w = (float)__ldg(p_img_w);

    // input base: raw[b, a*6 + f, h, w], channel stride = HW
    const size_t in_base = ((size_t)(b * 18 + a * 6) << 14) + (h << 7) + w;

    const float r0 = __ldg(raw + in_base);
    const float r1 = __ldg(raw + in_base + 1 * HW);
    const float r2 = __ldg(raw + in_base + 2 * HW);
    const float r3 = __ldg(raw + in_base + 3 * HW);
    const float r4 = __ldg(raw + in_base + 4 * HW);
    const float r5 = __ldg(raw + in_base + 5 * HW);

    const float aw = __ldg(anchors + 2 * a);
    const float ah = __ldg(anchors + 2 * a + 1);

    const float px   = (fsig(r0) + (float)w) * (1.0f / (float)NW) * img_w;
    const float py   = (fsig(r1) + (float)h) * (1.0f / (float)NH) * img_h;
    const float pw   = __expf(r2) * aw;
    const float ph   = __expf(r3) * ah;
    const float pa   = fsig(r4) * 360.0f - 180.0f;
    const float conf = fsig(r5);

    // stage in output order (t*6 + f), contiguous across the block
    float* sp = s + tl * 6;
    sp[0] = px;  sp[1] = py;  sp[2] = pw;
    sp[3] = ph;  sp[4] = pa;  sp[5] = conf;

    __syncthreads();

    // flush block's contiguous span: TPB*6 = 1536 floats = 384 float4
    float4* ob = reinterpret_cast<float4*>(out + (size_t)blockIdx.x * (TPB * 6));
    const float4* sv = reinterpret_cast<const float4*>(s);
    #pragma unroll
    for (int j = tl; j < TPB * 6 / 4; j += TPB) {
        ob[j] = sv[j];
    }
}

extern "C" void kernel_launch(void* const* d_in, const int* in_sizes, int n_in,
                              void* d_out, int out_size)
{
    const float* raw     = (const float*)d_in[0];
    const float* anchors = (const float*)d_in[1];
    const int*   img_h   = (const int*)d_in[2];
    const int*   img_w   = (const int*)d_in[3];
    float* out = (float*)d_out;

    const int blocks = CELLS / TPB;  // 12288
    rapid_decode_kernel<<<blocks, TPB>>>(raw, anchors, img_h, img_w, out);
}